// round 15
// baseline (speedup 1.0000x reference)
#include <cuda_runtime.h>
#include <cuda_fp16.h>
#include <cstdint>
#include <cstring>

// Problem constants (fixed by the dataset)
#define NODES 100000
#define RELS  8
#define HF    128
#define HT    128
#define NNZ   1600000
#define NSEG  (NODES * RELS)          // 800000 segments (row = rel*NODES + dst)
#define SEGPAD 802816                  // NSEG padded to 4096 multiple for scan
#define MBLK  ((NODES + 127) / 128)

// ---------------- scratch (__device__ globals; no allocations allowed) ------
__device__ __half g_nodes16[(size_t)NODES * HF];   // 25.6 MB, L2-resident
__device__ __half g_Wh[RELS * HF * HT];            // weights fp16 (256 KB)
__device__ int   g_deg[SEGPAD];
__device__ int   g_off[SEGPAD];
__device__ int   g_cursor[SEGPAD];
__device__ int2  g_e[NNZ];            // {src, val bits}; segment-sorted

// ---------------- helpers ----------------------------------------------------
__device__ __forceinline__ uint32_t smem_u32(const void* p) {
    uint32_t a;
    asm("{ .reg .u64 t; cvta.to.shared.u64 t, %1; cvt.u32.u64 %0, t; }"
        : "=r"(a) : "l"(p));
    return a;
}

__device__ __forceinline__ void ldsm_x4(uint32_t* r, uint32_t addr) {
    asm volatile("ldmatrix.sync.aligned.m8n8.x4.shared.b16 {%0,%1,%2,%3}, [%4];"
                 : "=r"(r[0]), "=r"(r[1]), "=r"(r[2]), "=r"(r[3]) : "r"(addr));
}

__device__ __forceinline__ void mma16816h(float* c, const uint32_t* a,
                                          const uint32_t* b) {
    asm volatile(
        "mma.sync.aligned.m16n8k16.row.col.f32.f16.f16.f32 "
        "{%0,%1,%2,%3}, {%4,%5,%6,%7}, {%8,%9}, {%0,%1,%2,%3};"
        : "+f"(c[0]), "+f"(c[1]), "+f"(c[2]), "+f"(c[3])
        : "r"(a[0]), "r"(a[1]), "r"(a[2]), "r"(a[3]), "r"(b[0]), "r"(b[1]));
}

// ---------------- fp32 -> fp16 conversions -----------------------------------
__global__ void k_wconv(const float* __restrict__ weights) {
    int i = blockIdx.x * blockDim.x + threadIdx.x;
    if (i >= RELS * HF * HT) return;
    g_Wh[i] = __float2half_rn(weights[i]);
}

__global__ void k_nconv(const float* __restrict__ nodes) {
    int i = blockIdx.x * blockDim.x + threadIdx.x;   // one float4 per thread
    if (i >= NODES * HF / 4) return;
    float4 v = ((const float4*)nodes)[i];
    __half2 a = __floats2half2_rn(v.x, v.y);
    __half2 b = __floats2half2_rn(v.z, v.w);
    uint2 u;
    memcpy(&u.x, &a, 4); memcpy(&u.y, &b, 4);
    ((uint2*)g_nodes16)[i] = u;
}

// ---------------- CSR build over 800k (rel,dst) segments ---------------------
__global__ void k_zero_deg() {
    int i = blockIdx.x * blockDim.x + threadIdx.x;
    if (i * 4 < SEGPAD) ((int4*)g_deg)[i] = make_int4(0, 0, 0, 0);
}

__global__ void k_count(const int* __restrict__ rows) {
    int e = blockIdx.x * blockDim.x + threadIdx.x;
    if (e >= NNZ) return;
    int r = rows[e];
    if (r < 0 || r >= NSEG) return;
    atomicAdd(&g_deg[r], 1);
}

// single-block warp-shuffle exclusive scan over g_deg -> g_off / g_cursor
__global__ void k_scan() {
    __shared__ int wsum[32];
    __shared__ int s_total;
    int tid = threadIdx.x, lane = tid & 31, wid = tid >> 5;
    int carry = 0;
    for (int base = 0; base < SEGPAD; base += 4096) {
        int idx = base + tid * 4;
        int4 v = *(const int4*)&g_deg[idx];
        int sum = v.x + v.y + v.z + v.w;
        int incl = sum;
        #pragma unroll
        for (int o = 1; o < 32; o <<= 1) {
            int n = __shfl_up_sync(0xffffffffu, incl, o);
            if (lane >= o) incl += n;
        }
        if (lane == 31) wsum[wid] = incl;
        __syncthreads();
        if (wid == 0) {
            int ws = wsum[lane];
            int wi = ws;
            #pragma unroll
            for (int o = 1; o < 32; o <<= 1) {
                int n = __shfl_up_sync(0xffffffffu, wi, o);
                if (lane >= o) wi += n;
            }
            wsum[lane] = wi - ws;                 // exclusive warp offsets
            if (lane == 31) s_total = wi;         // chunk total
        }
        __syncthreads();
        int ex = carry + wsum[wid] + (incl - sum);
        int4 o;
        o.x = ex; o.y = ex + v.x; o.z = o.y + v.y; o.w = o.z + v.z;
        *(int4*)&g_off[idx]    = o;
        *(int4*)&g_cursor[idx] = o;
        carry += s_total;
        __syncthreads();
    }
}

__global__ void k_scatter(const int* __restrict__ rows,
                          const int* __restrict__ cols,
                          const float* __restrict__ vals) {
    int e = blockIdx.x * blockDim.x + threadIdx.x;
    if (e >= NNZ) return;
    int r   = rows[e];
    int src = cols[e];
    if (r < 0 || r >= NSEG) return;
    if (src < 0 || src >= NODES) return;
    int pos = atomicAdd(&g_cursor[r], 1);
    g_e[pos] = make_int2(src, __float_as_int(vals[e]));
}

// ---------------- fused SpMM-tile + per-relation mma + relu ------------------
// CTA = 128 dst nodes. For each rel: build P[dst][j] = sum val*nodes16[src][j]
// in SMEM (fp16), stage W_r, one mma pass; accumulate out across rels in regs.
#define PITCH 136                        // fp16 per smem row (conflict-free ldsm)
#define TILE_B (128 * PITCH * 2)         // 34816 bytes
#define SM_P 0
#define SM_W TILE_B
#define FUSED_SMEM (2 * TILE_B)          // 69632 B -> 2 CTAs/SM

__global__ __launch_bounds__(256, 2)
void k_fused(float* __restrict__ out) {
    extern __shared__ char smem[];
    const uint32_t sbase = smem_u32(smem);

    const int tid  = threadIdx.x;
    const int lane = tid & 31;
    const int wid  = tid >> 5;
    const int mb   = blockIdx.x;

    // warp tiling for mma: 2 x 4 warp grid of 64x32 tiles (proven mapping)
    const int warp_m = wid & 1;
    const int warp_n = wid >> 1;
    const int g = lane >> 2;
    const int q = lane & 3;
    const int a_row = (lane & 7) + ((lane >> 3) & 1) * 8;
    const int a_k8  = (lane >> 4) * 8;
    const int b_n   = (lane & 7) + (lane >> 4) * 8;
    const int b_k8  = ((lane >> 3) & 1) * 8;

    const uint2* N2  = (const uint2*)g_nodes16;   // 32 uint2 per node row
    const uint2* Wh2 = (const uint2*)g_Wh;

    float acc[4][4][4];
    #pragma unroll
    for (int mi = 0; mi < 4; mi++)
        #pragma unroll
        for (int ni = 0; ni < 4; ni++)
            #pragma unroll
            for (int e = 0; e < 4; e++) acc[mi][ni][e] = 0.f;

    for (int rel = 0; rel < RELS; rel++) {
        // ---- stage W tile for this relation ---------------------------------
        #pragma unroll
        for (int t = 0; t < 16; t++) {
            int fi  = tid + t * 256;
            int row = fi >> 5;
            int c4  = fi & 31;
            uint32_t off = (uint32_t)(row * PITCH + c4 * 4) * 2;
            *(uint2*)(smem + SM_W + off) = Wh2[rel * 4096 + fi];
        }

        // ---- build P tile: warp handles 16 dst rows, segmented gather ------
        {
            int seg_base = rel * NODES + mb * 128;
            #pragma unroll 1
            for (int d = 0; d < 16; d++) {
                int row = wid * 16 + d;
                int dst = mb * 128 + row;
                float4 a = make_float4(0.f, 0.f, 0.f, 0.f);
                if (dst < NODES) {
                    int lo = g_off[seg_base + row];
                    int hi = g_off[seg_base + row + 1];
                    int e = lo;
                    for (; e + 1 < hi; e += 2) {
                        int2 e0 = g_e[e];
                        int2 e1 = g_e[e + 1];
                        float v0 = __int_as_float(e0.y);
                        float v1 = __int_as_float(e1.y);
                        uint2 u0 = N2[(size_t)e0.x * 32 + lane];
                        uint2 u1 = N2[(size_t)e1.x * 32 + lane];
                        float2 f0 = __half22float2(*(__half2*)&u0.x);
                        float2 f1 = __half22float2(*(__half2*)&u0.y);
                        float2 f2 = __half22float2(*(__half2*)&u1.x);
                        float2 f3 = __half22float2(*(__half2*)&u1.y);
                        a.x = fmaf(v0, f0.x, a.x); a.y = fmaf(v0, f0.y, a.y);
                        a.z = fmaf(v0, f1.x, a.z); a.w = fmaf(v0, f1.y, a.w);
                        a.x = fmaf(v1, f2.x, a.x); a.y = fmaf(v1, f2.y, a.y);
                        a.z = fmaf(v1, f3.x, a.z); a.w = fmaf(v1, f3.y, a.w);
                    }
                    if (e < hi) {
                        int2 ed = g_e[e];
                        float v = __int_as_float(ed.y);
                        uint2 u = N2[(size_t)ed.x * 32 + lane];
                        float2 f0 = __half22float2(*(__half2*)&u.x);
                        float2 f1 = __half22float2(*(__half2*)&u.y);
                        a.x = fmaf(v, f0.x, a.x); a.y = fmaf(v, f0.y, a.y);
                        a.z = fmaf(v, f1.x, a.z); a.w = fmaf(v, f1.y, a.w);
                    }
                }
                __half2 p0 = __floats2half2_rn(a.x, a.y);
                __half2 p1 = __floats2half2_rn(a.z, a.w);
                uint2 pu;
                memcpy(&pu.x, &p0, 4); memcpy(&pu.y, &p1, 4);
                *(uint2*)(smem + SM_P + (uint32_t)(row * PITCH + lane * 4) * 2) = pu;
            }
        }
        __syncthreads();

        // ---- one fp16 mma pass: acc += P @ W_r^T ----------------------------
        #pragma unroll
        for (int ks = 0; ks < 8; ks++) {
            const int kb = ks * 16;
            uint32_t ap[4][4];
            #pragma unroll
            for (int mi = 0; mi < 4; mi++) {
                int r = warp_m * 64 + mi * 16 + a_row;
                ldsm_x4(ap[mi], sbase + SM_P + (uint32_t)(r * PITCH + kb + a_k8) * 2);
            }
            uint32_t bh[2][4];
            #pragma unroll
            for (int nj = 0; nj < 2; nj++) {
                int n = warp_n * 32 + nj * 16 + b_n;
                ldsm_x4(bh[nj], sbase + SM_W + (uint32_t)(n * PITCH + kb + b_k8) * 2);
            }
            #pragma unroll
            for (int mi = 0; mi < 4; mi++)
                #pragma unroll
                for (int ni = 0; ni < 4; ni++)
                    mma16816h(acc[mi][ni], ap[mi], &bh[ni >> 1][(ni & 1) * 2]);
        }
        __syncthreads();   // protect P/W before next relation overwrites
    }

    // ---- epilogue: relu + write out (fp32) ----------------------------------
    #pragma unroll
    for (int mi = 0; mi < 4; mi++) {
        int r0 = mb * 128 + warp_m * 64 + mi * 16 + g;
        int r1 = r0 + 8;
        #pragma unroll
        for (int ni = 0; ni < 4; ni++) {
            int col = warp_n * 32 + ni * 8 + q * 2;
            if (r0 < NODES)
                *(float2*)&out[(size_t)r0 * HT + col] =
                    make_float2(fmaxf(acc[mi][ni][0], 0.f),
                                fmaxf(acc[mi][ni][1], 0.f));
            if (r1 < NODES)
                *(float2*)&out[(size_t)r1 * HT + col] =
                    make_float2(fmaxf(acc[mi][ni][2], 0.f),
                                fmaxf(acc[mi][ni][3], 0.f));
        }
    }
}

// ---------------- launch -----------------------------------------------------
extern "C" void kernel_launch(void* const* d_in, const int* in_sizes, int n_in,
                              void* d_out, int out_size) {
    const float* nodes   = (const float*)d_in[0];
    const int*   indices = (const int*)d_in[1];   // int32 (JAX x64 disabled)
    const float* values  = (const float*)d_in[2];
    const float* weights = (const float*)d_in[3];
    float*       out     = (float*)d_out;

    const int* rows = indices;
    const int* cols = indices + NNZ;

    static cudaStream_t s_side = nullptr;
    static cudaEvent_t  ev_fork = nullptr, ev_join = nullptr;
    if (s_side == nullptr) {
        cudaStreamCreateWithFlags(&s_side, cudaStreamNonBlocking);
        cudaEventCreateWithFlags(&ev_fork, cudaEventDisableTiming);
        cudaEventCreateWithFlags(&ev_join, cudaEventDisableTiming);
        cudaFuncSetAttribute(k_fused,
                             cudaFuncAttributeMaxDynamicSharedMemorySize,
                             FUSED_SMEM);
    }

    // fork
    cudaEventRecord(ev_fork, 0);
    cudaStreamWaitEvent(s_side, ev_fork, 0);

    // main stream: fp16 conversions (cheap)
    k_wconv<<<(RELS * HF * HT + 255) / 256, 256>>>(weights);
    k_nconv<<<(NODES * HF / 4 + 255) / 256, 256>>>(nodes);

    // side stream: segment-CSR build (independent)
    k_zero_deg<<<(SEGPAD / 4 + 255) / 256, 256, 0, s_side>>>();
    k_count<<<(NNZ + 255) / 256, 256, 0, s_side>>>(rows);
    k_scan<<<1, 1024, 0, s_side>>>();
    k_scatter<<<(NNZ + 255) / 256, 256, 0, s_side>>>(rows, cols, values);

    // join, then fused SpMM + GEMM + relu
    cudaEventRecord(ev_join, s_side);
    cudaStreamWaitEvent(0, ev_join, 0);
    k_fused<<<MBLK, 256, FUSED_SMEM>>>(out);
}

// round 16
// speedup vs baseline: 2.2946x; 2.2946x over previous
#include <cuda_runtime.h>
#include <cuda_fp16.h>
#include <cstdint>
#include <cstring>

// Problem constants (fixed by the dataset)
#define NODES 100000
#define RELS  8
#define HF    128
#define HT    128
#define NNZ   1600000
#define DEGPAD 102400            // NODES padded to int4 multiple for the scan
#define MBLK  ((NODES + 127) / 128)

// ---------------- scratch (__device__ globals; no allocations allowed) ------
__device__ __half g_H[(size_t)RELS * NODES * HT];  // 204.8 MB fp16
__device__ __half g_Wh[RELS * HF * HT];            // weights rounded to fp16
__device__ int   g_deg[DEGPAD];
__device__ int   g_off[DEGPAD];
__device__ int   g_cursor[DEGPAD];
__device__ int2  g_e[NNZ];       // {src | rel<<17, val bits}

// ---------------- helpers ----------------------------------------------------
__device__ __forceinline__ uint32_t smem_u32(const void* p) {
    uint32_t a;
    asm("{ .reg .u64 t; cvta.to.shared.u64 t, %1; cvt.u32.u64 %0, t; }"
        : "=r"(a) : "l"(p));
    return a;
}

__device__ __forceinline__ void ldsm_x4(uint32_t* r, uint32_t addr) {
    asm volatile("ldmatrix.sync.aligned.m8n8.x4.shared.b16 {%0,%1,%2,%3}, [%4];"
                 : "=r"(r[0]), "=r"(r[1]), "=r"(r[2]), "=r"(r[3]) : "r"(addr));
}

__device__ __forceinline__ void mma16816h(float* c, const uint32_t* a,
                                          const uint32_t* b) {
    asm volatile(
        "mma.sync.aligned.m16n8k16.row.col.f32.f16.f16.f32 "
        "{%0,%1,%2,%3}, {%4,%5,%6,%7}, {%8,%9}, {%0,%1,%2,%3};"
        : "+f"(c[0]), "+f"(c[1]), "+f"(c[2]), "+f"(c[3])
        : "r"(a[0]), "r"(a[1]), "r"(a[2]), "r"(a[3]), "r"(b[0]), "r"(b[1]));
}

// ---------------- weight round: fp32 -> fp16 ---------------------------------
__global__ void k_wsplit(const float* __restrict__ weights) {
    int i = blockIdx.x * blockDim.x + threadIdx.x;
    if (i >= RELS * HF * HT) return;
    g_Wh[i] = __float2half_rn(weights[i]);
}

// ---------------- tensor-core pre-transform via mma.sync ---------------------
// H[r][n][i] = sum_j nodes[n][j] * W[r][i][j]   (fp16 in/out, single pass)
#define PITCH 136                       // fp16 per smem row (272 B, ldsm conflict-free)
#define TILE_B (128 * PITCH * 2)        // 34816 bytes per tile
#define SM_A 0
#define SM_B TILE_B
#define GEMM_SMEM (2 * TILE_B)          // 69632 B -> 2+ CTAs/SM

__global__ __launch_bounds__(256, 2)
void k_gemm_tc(const float* __restrict__ nodes) {
    extern __shared__ char smem[];
    const uint32_t sbase = smem_u32(smem);

    const int tid  = threadIdx.x;
    const int lane = tid & 31;
    const int wid  = tid >> 5;
    const int mb   = blockIdx.x;

    // ---- convert + stage A tile (fp16) once ---------------------------------
    #pragma unroll
    for (int t = 0; t < 16; t++) {
        int fi  = tid + t * 256;           // 0..4095 float4 slots
        int row = fi >> 5;
        int c4  = fi & 31;
        int gr  = mb * 128 + row;
        float4 v = (gr < NODES) ? ((const float4*)nodes)[(size_t)gr * 32 + c4]
                                : make_float4(0.f, 0.f, 0.f, 0.f);
        __half2 h0 = __floats2half2_rn(v.x, v.y);
        __half2 h1 = __floats2half2_rn(v.z, v.w);
        uint2 hu;
        memcpy(&hu.x, &h0, 4); memcpy(&hu.y, &h1, 4);
        *(uint2*)(smem + SM_A + (uint32_t)(row * PITCH + c4 * 4) * 2) = hu;
    }

    // warp tiling: 2 x 4 warp grid of 64x32 tiles
    const int warp_m = wid & 1;
    const int warp_n = wid >> 1;
    const int g = lane >> 2;               // output row group
    const int q = lane & 3;                // output col pair

    // ldmatrix lane addressing (A: m16k16 tiles; B: n16k16 tiles)
    const int a_row = (lane & 7) + ((lane >> 3) & 1) * 8;
    const int a_k8  = (lane >> 4) * 8;
    const int b_n   = (lane & 7) + (lane >> 4) * 8;
    const int b_k8  = ((lane >> 3) & 1) * 8;

    for (int rel = 0; rel < RELS; rel++) {
        // ---- stage B tile (fp16) for this relation --------------------------
        const uint2* Wh2 = (const uint2*)g_Wh;
        #pragma unroll
        for (int t = 0; t < 16; t++) {
            int fi  = tid + t * 256;       // i*32 + c4
            int row = fi >> 5;
            int c4  = fi & 31;
            *(uint2*)(smem + SM_B + (uint32_t)(row * PITCH + c4 * 4) * 2) =
                Wh2[rel * 4096 + fi];
        }
        __syncthreads();

        float acc[4][4][4];
        #pragma unroll
        for (int mi = 0; mi < 4; mi++)
            #pragma unroll
            for (int ni = 0; ni < 4; ni++)
                #pragma unroll
                for (int e = 0; e < 4; e++) acc[mi][ni][e] = 0.f;

        #pragma unroll
        for (int ks = 0; ks < 8; ks++) {
            const int kb = ks * 16;
            uint32_t ap[4][4];
            #pragma unroll
            for (int mi = 0; mi < 4; mi++) {
                int r = warp_m * 64 + mi * 16 + a_row;
                ldsm_x4(ap[mi], sbase + SM_A + (uint32_t)(r * PITCH + kb + a_k8) * 2);
            }
            uint32_t bh[2][4];
            #pragma unroll
            for (int nj = 0; nj < 2; nj++) {
                int n = warp_n * 32 + nj * 16 + b_n;
                ldsm_x4(bh[nj], sbase + SM_B + (uint32_t)(n * PITCH + kb + b_k8) * 2);
            }
            #pragma unroll
            for (int mi = 0; mi < 4; mi++)
                #pragma unroll
                for (int ni = 0; ni < 4; ni++)
                    mma16816h(acc[mi][ni], ap[mi], &bh[ni >> 1][(ni & 1) * 2]);
        }

        // ---- write D tile to g_H (fp16) ------------------------------------
        __half* Hrel = g_H + (size_t)rel * NODES * HT;
        #pragma unroll
        for (int mi = 0; mi < 4; mi++) {
            int r0 = mb * 128 + warp_m * 64 + mi * 16 + g;
            int r1 = r0 + 8;
            #pragma unroll
            for (int ni = 0; ni < 4; ni++) {
                int col = warp_n * 32 + ni * 8 + q * 2;
                if (r0 < NODES)
                    *(__half2*)&Hrel[(size_t)r0 * HT + col] =
                        __floats2half2_rn(acc[mi][ni][0], acc[mi][ni][1]);
                if (r1 < NODES)
                    *(__half2*)&Hrel[(size_t)r1 * HT + col] =
                        __floats2half2_rn(acc[mi][ni][2], acc[mi][ni][3]);
            }
        }
        __syncthreads();   // protect B smem before next relation's load
    }
}

// ---------------- CSR build --------------------------------------------------
__global__ void k_zero_deg() {
    int i = blockIdx.x * blockDim.x + threadIdx.x;
    if (i * 4 < DEGPAD) ((int4*)g_deg)[i] = make_int4(0, 0, 0, 0);
}

__global__ void k_count(const int* __restrict__ rows) {
    int e = blockIdx.x * blockDim.x + threadIdx.x;
    if (e >= NNZ) return;
    int r = rows[e];
    if (r < 0 || r >= NODES * RELS) return;
    atomicAdd(&g_deg[r % NODES], 1);
}

// single-block warp-shuffle exclusive scan over g_deg -> g_off / g_cursor
__global__ void k_scan() {
    __shared__ int wsum[32];
    __shared__ int s_total;
    int tid = threadIdx.x, lane = tid & 31, wid = tid >> 5;
    int carry = 0;
    for (int base = 0; base < NODES; base += 4096) {
        int idx = base + tid * 4;
        int4 v = *(const int4*)&g_deg[idx];
        int sum = v.x + v.y + v.z + v.w;
        int incl = sum;
        #pragma unroll
        for (int o = 1; o < 32; o <<= 1) {
            int n = __shfl_up_sync(0xffffffffu, incl, o);
            if (lane >= o) incl += n;
        }
        if (lane == 31) wsum[wid] = incl;
        __syncthreads();
        if (wid == 0) {
            int ws = wsum[lane];
            int wi = ws;
            #pragma unroll
            for (int o = 1; o < 32; o <<= 1) {
                int n = __shfl_up_sync(0xffffffffu, wi, o);
                if (lane >= o) wi += n;
            }
            wsum[lane] = wi - ws;                 // exclusive warp offsets
            if (lane == 31) s_total = wi;         // chunk total
        }
        __syncthreads();
        int ex = carry + wsum[wid] + (incl - sum);
        int4 o;
        o.x = ex; o.y = ex + v.x; o.z = o.y + v.y; o.w = o.z + v.z;
        *(int4*)&g_off[idx]    = o;
        *(int4*)&g_cursor[idx] = o;
        carry += s_total;
        __syncthreads();
    }
}

__global__ void k_scatter(const int* __restrict__ rows,
                          const int* __restrict__ cols,
                          const float* __restrict__ vals) {
    int e = blockIdx.x * blockDim.x + threadIdx.x;
    if (e >= NNZ) return;
    int r   = rows[e];
    int src = cols[e];
    if (r < 0 || r >= NODES * RELS) return;
    if (src < 0 || src >= NODES) return;
    int dst = r % NODES;
    int rel = r / NODES;
    int pos = atomicAdd(&g_cursor[dst], 1);
    g_e[pos] = make_int2(src | (rel << 17), __float_as_int(vals[e]));
}

// ---------------- gather: out[n] = relu( sum val * H[rel][src] ) --------------
// one warp per node; fp16 H rows (256 B), uint2 per lane; unroll-8, dual acc
__device__ __forceinline__ void acc_edge(float4& acc, int pk, float v,
                                         const uint2* __restrict__ H2, int lane) {
    size_t row = (size_t)((pk >> 17) & 7) * NODES + (pk & 0x1FFFF);
    uint2 u = H2[row * 32 + lane];
    __half2 h01 = *(__half2*)&u.x;
    __half2 h23 = *(__half2*)&u.y;
    float2 f01 = __half22float2(h01);
    float2 f23 = __half22float2(h23);
    acc.x = fmaf(v, f01.x, acc.x);
    acc.y = fmaf(v, f01.y, acc.y);
    acc.z = fmaf(v, f23.x, acc.z);
    acc.w = fmaf(v, f23.y, acc.w);
}

__global__ __launch_bounds__(256)
void k_gather(float* __restrict__ out) {
    int lane = threadIdx.x & 31;
    int n = blockIdx.x * 8 + (threadIdx.x >> 5);
    if (n >= NODES) return;

    int start = g_off[n];
    int end   = g_off[n + 1];
    float4 a0 = make_float4(0.f, 0.f, 0.f, 0.f);
    float4 a1 = make_float4(0.f, 0.f, 0.f, 0.f);
    const uint2* H2 = (const uint2*)g_H;
    const int4*  E4 = (const int4*)g_e;     // 2 edges per int4

    int e = start;
    for (; e + 7 < end; e += 8) {
        int j = e >> 1;
        if ((e & 1) == 0) {
            int4 p0 = E4[j], p1 = E4[j + 1], p2 = E4[j + 2], p3 = E4[j + 3];
            acc_edge(a0, p0.x, __int_as_float(p0.y), H2, lane);
            acc_edge(a1, p0.z, __int_as_float(p0.w), H2, lane);
            acc_edge(a0, p1.x, __int_as_float(p1.y), H2, lane);
            acc_edge(a1, p1.z, __int_as_float(p1.w), H2, lane);
            acc_edge(a0, p2.x, __int_as_float(p2.y), H2, lane);
            acc_edge(a1, p2.z, __int_as_float(p2.w), H2, lane);
            acc_edge(a0, p3.x, __int_as_float(p3.y), H2, lane);
            acc_edge(a1, p3.z, __int_as_float(p3.w), H2, lane);
        } else {
            int2 e0 = g_e[e],     e1 = g_e[e + 1], e2 = g_e[e + 2], e3 = g_e[e + 3];
            int2 e4 = g_e[e + 4], e5 = g_e[e + 5], e6 = g_e[e + 6], e7 = g_e[e + 7];
            acc_edge(a0, e0.x, __int_as_float(e0.y), H2, lane);
            acc_edge(a1, e1.x, __int_as_float(e1.y), H2, lane);
            acc_edge(a0, e2.x, __int_as_float(e2.y), H2, lane);
            acc_edge(a1, e3.x, __int_as_float(e3.y), H2, lane);
            acc_edge(a0, e4.x, __int_as_float(e4.y), H2, lane);
            acc_edge(a1, e5.x, __int_as_float(e5.y), H2, lane);
            acc_edge(a0, e6.x, __int_as_float(e6.y), H2, lane);
            acc_edge(a1, e7.x, __int_as_float(e7.y), H2, lane);
        }
    }
    for (; e < end; e++) {
        int2 ed = g_e[e];
        acc_edge(a0, ed.x, __int_as_float(ed.y), H2, lane);
    }

    float4 o;
    o.x = fmaxf(a0.x + a1.x, 0.f); o.y = fmaxf(a0.y + a1.y, 0.f);
    o.z = fmaxf(a0.z + a1.z, 0.f); o.w = fmaxf(a0.w + a1.w, 0.f);
    ((float4*)out)[(size_t)n * 32 + lane] = o;
}

// ---------------- launch -----------------------------------------------------
extern "C" void kernel_launch(void* const* d_in, const int* in_sizes, int n_in,
                              void* d_out, int out_size) {
    const float* nodes   = (const float*)d_in[0];
    const int*   indices = (const int*)d_in[1];   // int32 (JAX x64 disabled)
    const float* values  = (const float*)d_in[2];
    const float* weights = (const float*)d_in[3];
    float*       out     = (float*)d_out;

    const int* rows = indices;
    const int* cols = indices + NNZ;

    static cudaStream_t s_side = nullptr;
    static cudaEvent_t  ev_fork = nullptr, ev_join = nullptr;
    if (s_side == nullptr) {
        cudaStreamCreateWithFlags(&s_side, cudaStreamNonBlocking);
        cudaEventCreateWithFlags(&ev_fork, cudaEventDisableTiming);
        cudaEventCreateWithFlags(&ev_join, cudaEventDisableTiming);
        cudaFuncSetAttribute(k_gemm_tc,
                             cudaFuncAttributeMaxDynamicSharedMemorySize,
                             GEMM_SMEM);
    }

    // fork: side stream inherits capture dependency from the main stream
    cudaEventRecord(ev_fork, 0);
    cudaStreamWaitEvent(s_side, ev_fork, 0);

    // main stream: weight round + tensor-core pre-transform (fp16, 1 pass)
    k_wsplit<<<(RELS * HF * HT + 255) / 256, 256>>>(weights);
    k_gemm_tc<<<MBLK, 256, GEMM_SMEM>>>(nodes);

    // side stream: CSR-by-destination build (independent of GEMM)
    k_zero_deg<<<(DEGPAD / 4 + 255) / 256, 256, 0, s_side>>>();
    k_count<<<(NNZ + 255) / 256, 256, 0, s_side>>>(rows);
    k_scan<<<1, 1024, 0, s_side>>>();
    k_scatter<<<(NNZ + 255) / 256, 256, 0, s_side>>>(rows, cols, values);

    // join, then atomic-free aggregation + relu
    cudaEventRecord(ev_join, s_side);
    cudaStreamWaitEvent(0, ev_join, 0);
    k_gather<<<(NODES + 7) / 8, 256>>>(out);
}